// round 2
// baseline (speedup 1.0000x reference)
#include <cuda_runtime.h>

#define BB 32
#define TT 64
#define FF 128
#define DD 64
#define HH 4
#define KK 32
#define HK 128
#define QSCALE 0.17677669529663687f  // 1/sqrt(32)

// ---------------------------------------------------------------------------
// Temporal branch: one CTA per (b, f). Sequence length T=64.
// Shared: Xs[64][64], Qs/Ks/Vs/Os[64][129] (padded), Ss[64][64]
// ---------------------------------------------------------------------------
__global__ void __launch_bounds__(256, 1) temporal_kernel(
    const float* __restrict__ x,
    const float* __restrict__ wq, const float* __restrict__ bq,
    const float* __restrict__ wk, const float* __restrict__ bk,
    const float* __restrict__ wv, const float* __restrict__ bv,
    const float* __restrict__ wo, const float* __restrict__ bo,
    float* __restrict__ out)
{
    extern __shared__ float sm[];
    float* Xs = sm;                 // 64*64   = 4096
    float* Qs = Xs + 64 * 64;       // 64*129
    float* Ks = Qs + 64 * 129;
    float* Vs = Ks + 64 * 129;
    float* Os = Vs + 64 * 129;
    float* Ss = Os + 64 * 129;      // 64*64

    const int tid = threadIdx.x;
    const int bf  = blockIdx.x;
    const int b   = bf >> 7;        // F = 128
    const int f   = bf & 127;

    // ---- load X slice: x[b, t, f, :] for t in [0,64) ----
    {
        const float4* x4 = (const float4*)x;
        for (int i = tid; i < 64 * 16; i += 256) {
            int t = i >> 4, c = i & 15;
            ((float4*)Xs)[t * 16 + c] =
                x4[((((b * TT + t) * FF + f) * DD) >> 2) + c];
        }
    }
    __syncthreads();

    // ---- Q,K,V projections: [64, 128] each ----
    {
        const int hk  = tid & 127;
        const int th0 = tid >> 7;   // 0..1

        float wr[64];
        #pragma unroll
        for (int d = 0; d < 64; d++) wr[d] = wq[d * HK + hk];
        float bb = bq[hk];
        for (int t = th0; t < 64; t += 2) {
            float acc = bb;
            #pragma unroll
            for (int d = 0; d < 64; d++) acc += wr[d] * Xs[t * 64 + d];
            Qs[t * 129 + hk] = acc * QSCALE;
        }

        #pragma unroll
        for (int d = 0; d < 64; d++) wr[d] = wk[d * HK + hk];
        bb = bk[hk];
        for (int t = th0; t < 64; t += 2) {
            float acc = bb;
            #pragma unroll
            for (int d = 0; d < 64; d++) acc += wr[d] * Xs[t * 64 + d];
            Ks[t * 129 + hk] = acc;
        }

        #pragma unroll
        for (int d = 0; d < 64; d++) wr[d] = wv[d * HK + hk];
        bb = bv[hk];
        for (int t = th0; t < 64; t += 2) {
            float acc = bb;
            #pragma unroll
            for (int d = 0; d < 64; d++) acc += wr[d] * Xs[t * 64 + d];
            Vs[t * 129 + hk] = acc;
        }
    }
    __syncthreads();

    // ---- per-head attention ----
    for (int h = 0; h < HH; h++) {
        const int hb = h * 32;
        // scores S[q][s] = Q[q] . K[s]  (over this head's 32 dims)
        {
            const int s  = tid & 63;
            const int qg = tid >> 6;   // 0..3
            float kr[32];
            #pragma unroll
            for (int k = 0; k < 32; k++) kr[k] = Ks[s * 129 + hb + k];
            #pragma unroll 4
            for (int qi = 0; qi < 16; qi++) {
                int q = qg * 16 + qi;
                float acc = 0.f;
                #pragma unroll
                for (int k = 0; k < 32; k++) acc += Qs[q * 129 + hb + k] * kr[k];
                Ss[q * 64 + s] = acc;
            }
        }
        __syncthreads();
        // softmax over rows (warp per row)
        {
            const int warp = tid >> 5, lane = tid & 31;
            for (int r = warp; r < 64; r += 8) {
                float v0 = Ss[r * 64 + lane];
                float v1 = Ss[r * 64 + 32 + lane];
                float m = fmaxf(v0, v1);
                #pragma unroll
                for (int o = 16; o > 0; o >>= 1)
                    m = fmaxf(m, __shfl_xor_sync(0xffffffffu, m, o));
                float e0 = __expf(v0 - m), e1 = __expf(v1 - m);
                float su = e0 + e1;
                #pragma unroll
                for (int o = 16; o > 0; o >>= 1)
                    su += __shfl_xor_sync(0xffffffffu, su, o);
                float inv = __frcp_rn(su);
                Ss[r * 64 + lane]      = e0 * inv;
                Ss[r * 64 + 32 + lane] = e1 * inv;
            }
        }
        __syncthreads();
        // O[q][hb+k] = sum_s P[q][s] * V[s][hb+k]
        {
            const int k  = tid & 31;
            const int qg = tid >> 5;   // 0..7
            float vr[64];
            #pragma unroll
            for (int s2 = 0; s2 < 64; s2++) vr[s2] = Vs[s2 * 129 + hb + k];
            #pragma unroll
            for (int qi = 0; qi < 8; qi++) {
                int q = qg * 8 + qi;
                float acc = 0.f;
                #pragma unroll
                for (int s2 = 0; s2 < 64; s2++) acc += Ss[q * 64 + s2] * vr[s2];
                Os[q * 129 + hb + k] = acc;
            }
        }
        __syncthreads();
    }

    // ---- output projection: out[b,t,f,d] = O[t] . wo[:,d] + bo[d] ----
    {
        const int d  = tid & 63;
        const int tg = tid >> 6;   // 0..3
        float acc[16];
        #pragma unroll
        for (int i = 0; i < 16; i++) acc[i] = 0.f;
        #pragma unroll
        for (int c = 0; c < 2; c++) {
            float wr[64];
            #pragma unroll
            for (int j = 0; j < 64; j++) wr[j] = wo[(c * 64 + j) * DD + d];
            #pragma unroll
            for (int qi = 0; qi < 16; qi++) {
                int q = tg * 16 + qi;
                float a = acc[qi];
                #pragma unroll
                for (int j = 0; j < 64; j++) a += Os[q * 129 + c * 64 + j] * wr[j];
                acc[qi] = a;
            }
        }
        float bod = bo[d];
        #pragma unroll
        for (int qi = 0; qi < 16; qi++) {
            int t = tg * 16 + qi;
            out[((b * TT + t) * FF + f) * DD + d] = acc[qi] + bod;
        }
    }
}

// ---------------------------------------------------------------------------
// Feature branch: one CTA per (b, t). Sequence length F=128. Per-head Q/K/V.
// Shared: Xs[128][64], Qh/Kh/Vh[128][33] (padded), Os[128][128], Ss[128][128]
// Adds into out (temporal kernel ran first).
// ---------------------------------------------------------------------------
__global__ void __launch_bounds__(256, 1) feature_kernel(
    const float* __restrict__ x,
    const float* __restrict__ wq, const float* __restrict__ bq,
    const float* __restrict__ wk, const float* __restrict__ bk,
    const float* __restrict__ wv, const float* __restrict__ bv,
    const float* __restrict__ wo, const float* __restrict__ bo,
    float* __restrict__ out)
{
    extern __shared__ float sm[];
    float* Xs = sm;                  // 128*64 = 8192
    float* Qh = Xs + 128 * 64;       // 128*33
    float* Kh = Qh + 128 * 33;
    float* Vh = Kh + 128 * 33;
    float* Os = Vh + 128 * 33;       // 128*128
    float* Ss = Os + 128 * 128;      // 128*128

    const int tid = threadIdx.x;
    const int bt  = blockIdx.x;
    const int b   = bt >> 6;         // T = 64
    const int t   = bt & 63;

    // ---- load X slice: x[b, t, :, :] (contiguous 8192 floats) ----
    {
        const float4* x4 = (const float4*)(x + (size_t)(b * TT + t) * FF * DD);
        float4* xs4 = (float4*)Xs;
        for (int i = tid; i < 2048; i += 256) xs4[i] = x4[i];
    }
    __syncthreads();

    for (int h = 0; h < HH; h++) {
        const int hb = h * 32;
        // per-head Q,K,V projections: [128, 32]
        {
            const int k  = tid & 31;
            const int fg = tid >> 5;   // 0..7
            float wr[64];

            #pragma unroll
            for (int d = 0; d < 64; d++) wr[d] = wq[d * HK + hb + k];
            float bb = bq[hb + k];
            #pragma unroll 2
            for (int fi = 0; fi < 16; fi++) {
                int fr = fg * 16 + fi;
                float acc = bb;
                #pragma unroll
                for (int d = 0; d < 64; d++) acc += wr[d] * Xs[fr * 64 + d];
                Qh[fr * 33 + k] = acc * QSCALE;
            }

            #pragma unroll
            for (int d = 0; d < 64; d++) wr[d] = wk[d * HK + hb + k];
            bb = bk[hb + k];
            #pragma unroll 2
            for (int fi = 0; fi < 16; fi++) {
                int fr = fg * 16 + fi;
                float acc = bb;
                #pragma unroll
                for (int d = 0; d < 64; d++) acc += wr[d] * Xs[fr * 64 + d];
                Kh[fr * 33 + k] = acc;
            }

            #pragma unroll
            for (int d = 0; d < 64; d++) wr[d] = wv[d * HK + hb + k];
            bb = bv[hb + k];
            #pragma unroll 2
            for (int fi = 0; fi < 16; fi++) {
                int fr = fg * 16 + fi;
                float acc = bb;
                #pragma unroll
                for (int d = 0; d < 64; d++) acc += wr[d] * Xs[fr * 64 + d];
                Vh[fr * 33 + k] = acc;
            }
        }
        __syncthreads();
        // scores S[q][s], q,s in [0,128)
        {
            const int s  = tid & 127;
            const int qg = tid >> 7;   // 0..1
            float kr[32];
            #pragma unroll
            for (int k = 0; k < 32; k++) kr[k] = Kh[s * 33 + k];
            #pragma unroll 4
            for (int qi = 0; qi < 64; qi++) {
                int q = qg * 64 + qi;
                float acc = 0.f;
                #pragma unroll
                for (int k = 0; k < 32; k++) acc += Qh[q * 33 + k] * kr[k];
                Ss[q * 128 + s] = acc;
            }
        }
        __syncthreads();
        // softmax over 128-wide rows (warp per row)
        {
            const int warp = tid >> 5, lane = tid & 31;
            for (int r = warp; r < 128; r += 8) {
                float v0 = Ss[r * 128 + lane];
                float v1 = Ss[r * 128 + 32 + lane];
                float v2 = Ss[r * 128 + 64 + lane];
                float v3 = Ss[r * 128 + 96 + lane];
                float m = fmaxf(fmaxf(v0, v1), fmaxf(v2, v3));
                #pragma unroll
                for (int o = 16; o > 0; o >>= 1)
                    m = fmaxf(m, __shfl_xor_sync(0xffffffffu, m, o));
                float e0 = __expf(v0 - m), e1 = __expf(v1 - m);
                float e2 = __expf(v2 - m), e3 = __expf(v3 - m);
                float su = (e0 + e1) + (e2 + e3);
                #pragma unroll
                for (int o = 16; o > 0; o >>= 1)
                    su += __shfl_xor_sync(0xffffffffu, su, o);
                float inv = __frcp_rn(su);
                Ss[r * 128 + lane]      = e0 * inv;
                Ss[r * 128 + 32 + lane] = e1 * inv;
                Ss[r * 128 + 64 + lane] = e2 * inv;
                Ss[r * 128 + 96 + lane] = e3 * inv;
            }
        }
        __syncthreads();
        // O[q][hb+k] = sum_s P[q][s] * V[s][k]   (s chunked 2x64 for regs)
        {
            const int k  = tid & 31;
            const int qg = tid >> 5;   // 0..7
            float acc[16];
            #pragma unroll
            for (int i = 0; i < 16; i++) acc[i] = 0.f;
            #pragma unroll
            for (int sc = 0; sc < 2; sc++) {
                float vr[64];
                #pragma unroll
                for (int j = 0; j < 64; j++) vr[j] = Vh[(sc * 64 + j) * 33 + k];
                #pragma unroll
                for (int qi = 0; qi < 16; qi++) {
                    int q = qg * 16 + qi;
                    float a = acc[qi];
                    #pragma unroll
                    for (int j = 0; j < 64; j++)
                        a += Ss[q * 128 + sc * 64 + j] * vr[j];
                    acc[qi] = a;
                }
            }
            #pragma unroll
            for (int qi = 0; qi < 16; qi++)
                Os[(qg * 16 + qi) * 128 + hb + k] = acc[qi];
        }
        __syncthreads();
    }

    // ---- output projection + accumulate into out ----
    {
        const int d  = tid & 63;
        const int tg = tid >> 6;   // 0..3
        float acc[32];
        #pragma unroll
        for (int i = 0; i < 32; i++) acc[i] = 0.f;
        #pragma unroll
        for (int c = 0; c < 2; c++) {
            float wr[64];
            #pragma unroll
            for (int j = 0; j < 64; j++) wr[j] = wo[(c * 64 + j) * DD + d];
            #pragma unroll
            for (int qi = 0; qi < 32; qi++) {
                int q = tg * 32 + qi;
                float a = acc[qi];
                #pragma unroll
                for (int j = 0; j < 64; j++) a += Os[q * 128 + c * 64 + j] * wr[j];
                acc[qi] = a;
            }
        }
        float bod = bo[d];
        #pragma unroll
        for (int qi = 0; qi < 32; qi++) {
            int fr = tg * 32 + qi;
            size_t idx = ((size_t)(b * TT + t) * FF + fr) * DD + d;
            out[idx] += acc[qi] + bod;
        }
    }
}

// ---------------------------------------------------------------------------
extern "C" void kernel_launch(void* const* d_in, const int* in_sizes, int n_in,
                              void* d_out, int out_size)
{
    const float* x = (const float*)d_in[0];
    const float *tqw, *tqb, *tkw, *tkb, *tvw, *tvb, *tow, *tob;
    const float *fqw, *fqb, *fkw, *fkb, *fvw, *fvb, *fow, *fob;

    // Disambiguate input ordering: reference-signature order has to_b (size 64)
    // at index 8; setup_inputs dict order has fq_b (size 128) there.
    if (in_sizes[8] == 64) {
        tqw = (const float*)d_in[1];  tqb = (const float*)d_in[2];
        tkw = (const float*)d_in[3];  tkb = (const float*)d_in[4];
        tvw = (const float*)d_in[5];  tvb = (const float*)d_in[6];
        tow = (const float*)d_in[7];  tob = (const float*)d_in[8];
        fqw = (const float*)d_in[9];  fqb = (const float*)d_in[10];
        fkw = (const float*)d_in[11]; fkb = (const float*)d_in[12];
        fvw = (const float*)d_in[13]; fvb = (const float*)d_in[14];
        fow = (const float*)d_in[15]; fob = (const float*)d_in[16];
    } else {
        tqw = (const float*)d_in[1];  tqb = (const float*)d_in[2];
        tkw = (const float*)d_in[3];  tkb = (const float*)d_in[4];
        tvw = (const float*)d_in[5];  tvb = (const float*)d_in[6];
        fqw = (const float*)d_in[7];  fqb = (const float*)d_in[8];
        fkw = (const float*)d_in[9];  fkb = (const float*)d_in[10];
        fvw = (const float*)d_in[11]; fvb = (const float*)d_in[12];
        tow = (const float*)d_in[13]; tob = (const float*)d_in[14];
        fow = (const float*)d_in[15]; fob = (const float*)d_in[16];
    }

    float* out = (float*)d_out;

    const size_t sm_t = (size_t)(64 * 64 + 4 * 64 * 129 + 64 * 64) * sizeof(float);
    const size_t sm_f = (size_t)(128 * 64 + 3 * 128 * 33 + 2 * 128 * 128) * sizeof(float);

    cudaFuncSetAttribute(temporal_kernel,
                         cudaFuncAttributeMaxDynamicSharedMemorySize, (int)sm_t);
    cudaFuncSetAttribute(feature_kernel,
                         cudaFuncAttributeMaxDynamicSharedMemorySize, (int)sm_f);

    temporal_kernel<<<BB * FF, 256, sm_t>>>(x, tqw, tqb, tkw, tkb, tvw, tvb,
                                            tow, tob, out);
    feature_kernel<<<BB * TT, 256, sm_f>>>(x, fqw, fqb, fkw, fkb, fvw, fvb,
                                           fow, fob, out);
}